// round 15
// baseline (speedup 1.0000x reference)
#include <cuda_runtime.h>
#include <cuda_bf16.h>
#include <math.h>
#include <stdint.h>

#define BB 32
#define NN 577
#define DD 384
#define LL 12
#define NRPT 4
#define HH 1536
#define MMAX 580
#define MPAD 640
#define SROWS (BB * NN)   // 18464 rows: all stats buffers use this stride

// ---------------- scratch ----------------
__device__ float g_x[BB * NN * DD];
__device__ float g_hist[NRPT * BB * DD];
__device__ __nv_bfloat16 g_qbf[BB * NN * DD];      // q / prod bf16 staging
__device__ __nv_bfloat16 g_kbf[BB * MMAX * DD];    // k bf16 staging (s1-serial)
__device__ __nv_bfloat16 g_scbf[(size_t)BB * NN * MPAD];
__device__ uint8_t g_mem8[BB * MMAX * DD];
__device__ uint8_t g_attn8[(size_t)BB * NN * MPAD];
__device__ uint8_t g_h8[(size_t)BB * NN * HH];
__device__ uint8_t g_k8L[(size_t)LL * BB * MMAX * DD];   // per-layer k8
__device__ uint8_t g_vT8L[(size_t)LL * BB * DD * MPAD];  // per-layer vT8
__device__ uint8_t g_wqkv8[LL * 3 * DD * DD];
__device__ uint8_t g_wproj8[LL * DD * DD];
__device__ uint8_t g_wfc18[LL * HH * DD];
__device__ uint8_t g_wfc28[LL * DD * HH];
// row stats buffers: [6 slots][SROWS] of float2 (sum, sumsq)
__device__ float2 g_xs1[6 * SROWS];
__device__ float2 g_xs2[6 * SROWS];
__device__ float2 g_qst[6 * SROWS];
__device__ float2 g_pst[6 * SROWS];

// fp8 operand scales (powers of 2)
#define SC_W 32.0f
#define SC_LN 4.0f
#define SC_MEM 4.0f
#define SC_ATTN 16.0f
#define SC_V 8.0f
#define SC_H 16.0f

// ---------------- PTX helpers ----------------
__device__ __forceinline__ uint32_t smem_u32(const void* p) {
    uint32_t a;
    asm("{ .reg .u64 t; cvta.to.shared.u64 t, %1; cvt.u32.u64 %0, t; }" : "=r"(a) : "l"(p));
    return a;
}
__device__ __forceinline__ void cpasync16(uint32_t dst, const void* src, int srcsize) {
    asm volatile("cp.async.cg.shared.global [%0], [%1], 16, %2;" :: "r"(dst), "l"(src), "r"(srcsize));
}
__device__ __forceinline__ void cpcommit() { asm volatile("cp.async.commit_group;" ::: "memory"); }
__device__ __forceinline__ void cpwait1() { asm volatile("cp.async.wait_group 1;" ::: "memory"); }
__device__ __forceinline__ void cpwait0() { asm volatile("cp.async.wait_group 0;" ::: "memory"); }

__device__ __forceinline__ uint16_t pack_e4m3(float lo, float hi) {
    uint16_t r;
    asm("cvt.rn.satfinite.e4m3x2.f32 %0, %1, %2;" : "=h"(r) : "f"(hi), "f"(lo));
    return r;
}
__device__ __forceinline__ float2 bf2_to_f2(uint32_t w) {
    __nv_bfloat162 b = *(__nv_bfloat162*)&w;
    return make_float2(__bfloat162float(b.x), __bfloat162float(b.y));
}

#define LDSM4(r0, r1, r2, r3, a)                                                     \
    asm volatile("ldmatrix.sync.aligned.m8n8.x4.shared.b16 {%0,%1,%2,%3}, [%4];"     \
                 : "=r"(r0), "=r"(r1), "=r"(r2), "=r"(r3) : "r"(a))

#define MMAFP8(d, av, bv)                                                            \
    asm volatile("mma.sync.aligned.m16n8k32.row.col.f32.e4m3.e4m3.f32 "              \
                 "{%0,%1,%2,%3},{%4,%5,%6,%7},{%8,%9},{%0,%1,%2,%3};"                \
                 : "+f"((d)[0]), "+f"((d)[1]), "+f"((d)[2]), "+f"((d)[3])            \
                 : "r"((av)[0]), "r"((av)[1]), "r"((av)[2]), "r"((av)[3]),           \
                   "r"((bv)[0]), "r"((bv)[1]))

__device__ __forceinline__ float gelu_exact(float v) {
    return 0.5f * v * (1.0f + erff(v * 0.70710678118654752f));
}

// ======== shared epilogue (both GEMMs): modes + optional row-stats partials ========
// mode 1: fp8 out, v = gelu(base+bias[gn])*oscale
// mode 2: f32 out, v = (base+bias[gn])*ls[gn] + res[..]
// mode 3: fp8 out, v = (base+bias[gm])*oscale; zero-fill [Nvalid, Npad)
// mode 4: bf16 out, v = base (+bias[gn]), stores cols < Npad
#define EPILOGUE()                                                                          \
    _Pragma("unroll")                                                                       \
    for (int mt = 0; mt < 2; mt++) {                                                        \
        _Pragma("unroll")                                                                   \
        for (int half = 0; half < 2; half++) {                                              \
            int gm = m0 + wm * 32 + mt * 16 + (lid >> 2) + half * 8;                        \
            bool mok = gm < Mrows;                                                          \
            float ssum = 0.f, ssq = 0.f;                                                    \
            _Pragma("unroll")                                                               \
            for (int nt = 0; nt < 8; nt++) {                                                \
                int c0 = n0 + wn * 64 + nt * 8 + (lid & 3) * 2;                             \
                float a0 = acc[mt][nt][half * 2] * alpha;                                   \
                float a1 = acc[mt][nt][half * 2 + 1] * alpha;                               \
                float v0 = 0.f, v1 = 0.f;                                                   \
                if (mode == 1) {                                                            \
                    v0 = gelu_exact(a0 + bias[c0]);                                         \
                    v1 = gelu_exact(a1 + bias[c0 + 1]);                                     \
                    if (mok) {                                                              \
                        uint8_t* C = (uint8_t*)Cv + (size_t)bz * zC;                        \
                        *(uint16_t*)(C + (size_t)gm * ldc + c0) =                           \
                            pack_e4m3(v0 * oscale, v1 * oscale);                            \
                    }                                                                       \
                } else if (mode == 2) {                                                     \
                    if (mok) {                                                              \
                        float* C = (float*)Cv + (size_t)bz * zC;                            \
                        float2 r = *(const float2*)(resp + (size_t)gm * ldc + c0);          \
                        v0 = (a0 + bias[c0]) * ls[c0] + r.x;                                \
                        v1 = (a1 + bias[c0 + 1]) * ls[c0 + 1] + r.y;                        \
                        *(float2*)(C + (size_t)gm * ldc + c0) = make_float2(v0, v1);        \
                    }                                                                       \
                } else if (mode == 3) {                                                     \
                    float bb = bias ? bias[gm] : 0.f;                                       \
                    v0 = (c0 < Nvalid) ? (a0 + bb) : 0.f;                                   \
                    v1 = (c0 + 1 < Nvalid) ? (a1 + bb) : 0.f;                               \
                    if (mok && c0 + 1 < Npad) {                                             \
                        uint8_t* C = (uint8_t*)Cv + (size_t)bz * zC;                        \
                        *(uint16_t*)(C + (size_t)gm * ldc + c0) =                           \
                            pack_e4m3(v0 * oscale, v1 * oscale);                            \
                    }                                                                       \
                } else {                                                                    \
                    float b0 = 0.f, b1 = 0.f;                                               \
                    if (bias) { b0 = bias[c0]; b1 = bias[c0 + 1]; }                         \
                    v0 = a0 + b0; v1 = a1 + b1;                                             \
                    if (mok && c0 + 1 < Npad) {                                             \
                        __nv_bfloat16* C = (__nv_bfloat16*)Cv + (size_t)bz * zC;            \
                        __nv_bfloat162 v;                                                   \
                        v.x = __float2bfloat16(v0); v.y = __float2bfloat16(v1);             \
                        *(__nv_bfloat162*)(C + (size_t)gm * ldc + c0) = v;                  \
                    }                                                                       \
                }                                                                           \
                ssum += v0 + v1;                                                            \
                ssq += v0 * v0 + v1 * v1;                                                   \
            }                                                                               \
            if (statsOut) {                                                                 \
                ssum += __shfl_xor_sync(0xffffffffu, ssum, 1);                              \
                ssum += __shfl_xor_sync(0xffffffffu, ssum, 2);                              \
                ssq += __shfl_xor_sync(0xffffffffu, ssq, 1);                                \
                ssq += __shfl_xor_sync(0xffffffffu, ssq, 2);                                \
                if ((lid & 3) == 0 && mok)                                                  \
                    statsOut[(blockIdx.x * 2 + wn) * SROWS + rowoff + gm] =                 \
                        make_float2(ssum, ssq);                                             \
            }                                                                               \
        }                                                                                   \
    }

// ================= kernel 1: plain fp8-A GEMM (3-stage ring) =================
#define SM_A(s) ((s) * 32768)
#define SM_B(s) ((s) * 32768 + 16384)
#define SMEM_G (3 * 32768 + 1024)

__global__ void __launch_bounds__(256, 2)
mma_gemm_nt(const uint8_t* __restrict__ A, const uint8_t* __restrict__ W,
            const float* __restrict__ bias, const float* __restrict__ ls,
            const float* __restrict__ res, void* __restrict__ Cv,
            float2* __restrict__ statsOut, long zSOut,
            int Mrows, int Nvalid, int Npad, int K, int lda, int ldw, int ldc,
            long zA, long zW, long zC, float alpha, float oscale, int mode) {
    extern __shared__ char smraw[];
    uint32_t sbase = (smem_u32(smraw) + 1023u) & ~1023u;
    int tid = threadIdx.x, wid = tid >> 5, lid = tid & 31;
    int bz = blockIdx.z;
    A += (size_t)bz * zA;
    W += (size_t)bz * zW;
    const float* resp = res ? res + (size_t)bz * zC : (const float*)0;
    long rowoff = (long)bz * zSOut;
    int m0 = blockIdx.y * 128, n0 = blockIdx.x * 128;
    int wm = wid & 3, wn = wid >> 2;

    float acc[2][8][4];
#pragma unroll
    for (int a = 0; a < 2; a++)
#pragma unroll
        for (int b = 0; b < 8; b++)
#pragma unroll
            for (int c = 0; c < 4; c++) acc[a][b][c] = 0.f;

    int nk = K >> 7;

#define LOADC_G(kc, s) do {                                                            \
    int _k0 = (kc) << 7;                                                               \
    _Pragma("unroll")                                                                  \
    for (int _i = 0; _i < 4; _i++) {                                                   \
        int _idx = tid + 256 * _i;                                                     \
        int _row = _idx >> 3, _g = _idx & 7;                                           \
        int _gm = m0 + _row;                                                           \
        int _pr = (_gm < Mrows) ? 16 : 0;                                              \
        const uint8_t* _src = A + (size_t)(_pr ? _gm : 0) * lda + _k0 + _g * 16;       \
        cpasync16(sbase + SM_A(s) + _row * 128 + (((_g ^ (_row & 7))) << 4), _src, _pr); \
    }                                                                                  \
    _Pragma("unroll")                                                                  \
    for (int _i = 0; _i < 4; _i++) {                                                   \
        int _idx = tid + 256 * _i;                                                     \
        int _row = _idx >> 3, _g = _idx & 7;                                           \
        int _gn = n0 + _row;                                                           \
        int _pr = (_gn < Nvalid) ? 16 : 0;                                             \
        const uint8_t* _src = W + (size_t)(_pr ? _gn : 0) * ldw + _k0 + _g * 16;       \
        cpasync16(sbase + SM_B(s) + _row * 128 + (((_g ^ (_row & 7))) << 4), _src, _pr); \
    }                                                                                  \
    cpcommit();                                                                        \
} while (0)

    LOADC_G(0, 0);
    if (nk > 1) LOADC_G(1, 1);
    int grp = lid >> 3, rin = lid & 7;
    int slot = 0;
    for (int i = 0; i < nk; i++) {
        if (i + 1 < nk) cpwait1(); else cpwait0();
        __syncthreads();
        if (i + 2 < nk) {
            int ns = slot + 2; if (ns >= 3) ns -= 3;
            LOADC_G(i + 2, ns);
        }
        int s = slot;
#pragma unroll
        for (int ks = 0; ks < 4; ks++) {
            uint32_t af[2][4], bf[8][2];
#pragma unroll
            for (int mt = 0; mt < 2; mt++) {
                int row = wm * 32 + mt * 16 + rin + (grp & 1) * 8;
                int kg = ks * 2 + (grp >> 1);
                uint32_t ad = sbase + SM_A(s) + row * 128 + ((kg ^ (row & 7)) << 4);
                LDSM4(af[mt][0], af[mt][1], af[mt][2], af[mt][3], ad);
            }
#pragma unroll
            for (int np = 0; np < 4; np++) {
                int row = wn * 64 + np * 16 + rin + (grp >> 1) * 8;
                int kg = ks * 2 + (grp & 1);
                uint32_t ad = sbase + SM_B(s) + row * 128 + ((kg ^ (row & 7)) << 4);
                LDSM4(bf[2 * np][0], bf[2 * np][1], bf[2 * np + 1][0], bf[2 * np + 1][1], ad);
            }
#pragma unroll
            for (int mt = 0; mt < 2; mt++)
#pragma unroll
                for (int nt = 0; nt < 8; nt++)
                    MMAFP8(acc[mt][nt], af[mt], bf[nt]);
        }
        slot++; if (slot >= 3) slot = 0;
    }
    EPILOGUE()
}

// ======= kernel 2: LN-on-load GEMM (A normalized from f32/bf16 src, K=384) =======
#define LB_OFF(s) ((s) * 16384)
#define LA_OFF(c) (49152 + (c) * 16384)
#define LMU_OFF 98304
#define LINV_OFF 98816
#define LW_OFF 99328
#define LBL_OFF 100864
#define SMEM_LNA (102400 + 1024)

__global__ void __launch_bounds__(256, 2)
gemm_lnA(const void* __restrict__ Asrc, int srcF32,
         const uint8_t* __restrict__ W, const float* __restrict__ bias,
         const float* __restrict__ ls, const float* __restrict__ res,
         const float* __restrict__ lnw, const float* __restrict__ lnb,
         const float2* __restrict__ statsIn, long zSIn,
         float2* __restrict__ statsOut, long zSOut, void* __restrict__ Cv,
         int Mrows, int Nvalid, int Npad, int lda, int ldw, int ldc,
         long zA, long zW, long zC, float alpha, float oscale, int mode) {
    extern __shared__ char smraw[];
    uint32_t sbase = (smem_u32(smraw) + 1023u) & ~1023u;
    char* salc = smraw + (sbase - smem_u32(smraw));
    float* smu = (float*)(salc + LMU_OFF);
    float* sinv = (float*)(salc + LINV_OFF);
    float* swl = (float*)(salc + LW_OFF);
    float* sbl = (float*)(salc + LBL_OFF);
    int tid = threadIdx.x, wid = tid >> 5, lid = tid & 31;
    int bz = blockIdx.z;
    const float* resp = res ? res + (size_t)bz * zC : (const float*)0;
    long rowoff = (long)bz * zSOut;
    int m0 = blockIdx.y * 128, n0 = blockIdx.x * 128;
    int wm = wid & 3, wn = wid >> 2;

    float acc[2][8][4];
#pragma unroll
    for (int a = 0; a < 2; a++)
#pragma unroll
        for (int b = 0; b < 8; b++)
#pragma unroll
            for (int c = 0; c < 4; c++) acc[a][b][c] = 0.f;

    const uint8_t* Wb = W + (size_t)bz * zW;

#define LOADB_L(kc, s) do {                                                            \
    int _k0 = (kc) << 7;                                                               \
    _Pragma("unroll")                                                                  \
    for (int _i = 0; _i < 4; _i++) {                                                   \
        int _idx = tid + 256 * _i;                                                     \
        int _row = _idx >> 3, _g = _idx & 7;                                           \
        int _gn = n0 + _row;                                                           \
        int _pr = (_gn < Nvalid) ? 16 : 0;                                             \
        const uint8_t* _src = Wb + (size_t)(_pr ? _gn : 0) * ldw + _k0 + _g * 16;      \
        cpasync16(sbase + LB_OFF(s) + _row * 128 + (((_g ^ (_row & 7))) << 4), _src, _pr); \
    }                                                                                  \
    cpcommit();                                                                        \
} while (0)

    LOADB_L(0, 0);
    LOADB_L(1, 1);

    // LN params and per-row stats -> smem
    for (int c = tid; c < DD; c += 256) {
        swl[c] = lnw[c] * SC_LN;
        sbl[c] = lnb[c] * SC_LN;
    }
    if (tid < 128) {
        int gm = m0 + tid;
        float mu = 0.f, iv = 0.f;
        if (gm < Mrows) {
            float s = 0.f, s2 = 0.f;
#pragma unroll
            for (int j = 0; j < 6; j++) {
                float2 p = statsIn[(size_t)j * SROWS + bz * zSIn + gm];
                s += p.x; s2 += p.y;
            }
            mu = s * (1.0f / DD);
            float var = s2 * (1.0f / DD) - mu * mu;
            iv = rsqrtf(fmaxf(var, 0.f) + 1e-6f);
        }
        smu[tid] = mu;
        sinv[tid] = iv;
    }
    __syncthreads();

    // convert A tile (128 rows x 384 cols) -> normalized fp8 in smem
#pragma unroll
    for (int it = 0; it < 12; it++) {
        int gid = tid + 256 * it;
        int ck = gid >> 10;
        int row = (gid >> 3) & 127;
        int g = gid & 7;
        int gm = m0 + row;
        int c0 = ck * 128 + g * 16;
        uint32_t pk[4] = {0, 0, 0, 0};
        if (gm < Mrows) {
            float mu = smu[row], iv = sinv[row];
            float vals[16];
            if (srcF32) {
                const float4* p = (const float4*)((const float*)Asrc + (size_t)bz * zA +
                                                  (size_t)gm * lda + c0);
#pragma unroll
                for (int q4 = 0; q4 < 4; q4++) {
                    float4 f = p[q4];
                    vals[q4 * 4 + 0] = f.x; vals[q4 * 4 + 1] = f.y;
                    vals[q4 * 4 + 2] = f.z; vals[q4 * 4 + 3] = f.w;
                }
            } else {
                const uint4* p = (const uint4*)((const __nv_bfloat16*)Asrc + (size_t)bz * zA +
                                                (size_t)gm * lda + c0);
#pragma unroll
                for (int h = 0; h < 2; h++) {
                    uint4 u = p[h];
                    float2 f0 = bf2_to_f2(u.x), f1 = bf2_to_f2(u.y);
                    float2 f2 = bf2_to_f2(u.z), f3 = bf2_to_f2(u.w);
                    vals[h * 8 + 0] = f0.x; vals[h * 8 + 1] = f0.y;
                    vals[h * 8 + 2] = f1.x; vals[h * 8 + 3] = f1.y;
                    vals[h * 8 + 4] = f2.x; vals[h * 8 + 5] = f2.y;
                    vals[h * 8 + 6] = f3.x; vals[h * 8 + 7] = f3.y;
                }
            }
#pragma unroll
            for (int q4 = 0; q4 < 4; q4++) {
                int c = c0 + q4 * 4;
                float o0 = (vals[q4 * 4 + 0] - mu) * iv * swl[c + 0] + sbl[c + 0];
                float o1 = (vals[q4 * 4 + 1] - mu) * iv * swl[c + 1] + sbl[c + 1];
                float o2 = (vals[q4 * 4 + 2] - mu) * iv * swl[c + 2] + sbl[c + 2];
                float o3 = (vals[q4 * 4 + 3] - mu) * iv * swl[c + 3] + sbl[c + 3];
                pk[q4] = (uint32_t)pack_e4m3(o0, o1) | ((uint32_t)pack_e4m3(o2, o3) << 16);
            }
        }
        *(uint4*)(salc + LA_OFF(ck) + row * 128 + ((g ^ (row & 7)) << 4)) =
            make_uint4(pk[0], pk[1], pk[2], pk[3]);
    }
    __syncthreads();

    int grp = lid >> 3, rin = lid & 7;
    for (int i = 0; i < 3; i++) {
        if (i + 1 < 3) cpwait1(); else cpwait0();
        __syncthreads();
        if (i + 2 < 3) LOADB_L(2, 2);
#pragma unroll
        for (int ks = 0; ks < 4; ks++) {
            uint32_t af[2][4], bf[8][2];
#pragma unroll
            for (int mt = 0; mt < 2; mt++) {
                int row = wm * 32 + mt * 16 + rin + (grp & 1) * 8;
                int kg = ks * 2 + (grp >> 1);
                uint32_t ad = sbase + LA_OFF(i) + row * 128 + ((kg ^ (row & 7)) << 4);
                LDSM4(af[mt][0], af[mt][1], af[mt][2], af[mt][3], ad);
            }
#pragma unroll
            for (int np = 0; np < 4; np++) {
                int row = wn * 64 + np * 16 + rin + (grp >> 1) * 8;
                int kg = ks * 2 + (grp & 1);
                uint32_t ad = sbase + LB_OFF(i) + row * 128 + ((kg ^ (row & 7)) << 4);
                LDSM4(bf[2 * np][0], bf[2 * np][1], bf[2 * np + 1][0], bf[2 * np + 1][1], ad);
            }
#pragma unroll
            for (int mt = 0; mt < 2; mt++)
#pragma unroll
                for (int nt = 0; nt < 8; nt++)
                    MMAFP8(acc[mt][nt], af[mt], bf[nt]);
        }
    }
    EPILOGUE()
}

// ---------------- small kernels ----------------
__global__ void copy_kernel(float* __restrict__ dst, const float* __restrict__ src, int n) {
    int i = blockIdx.x * 256 + threadIdx.x;
    if (i < n) dst[i] = src[i];
}
__global__ void cvt_w8_kernel(uint8_t* __restrict__ dst, const float* __restrict__ src, int npair) {
    int i = blockIdx.x * 256 + threadIdx.x;
    if (i >= npair) return;
    float2 v = *(const float2*)(src + 2 * i);
    *(uint16_t*)(dst + 2 * i) = pack_e4m3(v.x * SC_W, v.y * SC_W);
}
__global__ void save_cls_kernel(const float* __restrict__ x, float* __restrict__ hist_r) {
    int i = blockIdx.x * 256 + threadIdx.x;
    if (i >= BB * DD) return;
    int b = i / DD, d = i % DD;
    hist_r[i] = x[(size_t)b * NN * DD + d];
}
__global__ void restore_patches_kernel(float* __restrict__ x, const float* __restrict__ x_in) {
    int i = blockIdx.x * 256 + threadIdx.x;
    if (i >= BB * NN * DD) return;
    int tok = (i / DD) % NN;
    if (tok != 0) x[i] = x_in[i];
}
__global__ void build_mem8_kernel(uint8_t* __restrict__ mem, const float* __restrict__ x,
                                  const float* __restrict__ hist, int Mk) {
    int i = blockIdx.x * 256 + threadIdx.x;
    int npair = BB * Mk * (DD / 2);
    if (i >= npair) return;
    int d2 = i % (DD / 2);
    int t = (i / (DD / 2)) % Mk;
    int b = i / ((DD / 2) * Mk);
    const float* src;
    if (t < NN) src = x + ((size_t)b * NN + t) * DD + 2 * d2;
    else        src = hist + ((size_t)(t - NN) * BB + b) * DD + 2 * d2;
    float2 v = *(const float2*)src;
    *(uint16_t*)(mem + ((size_t)b * Mk + t) * DD + 2 * d2) = pack_e4m3(v.x * SC_MEM, v.y * SC_MEM);
}
// row stats of f32 x -> slot 0 (full), slots 1-5 zero
__global__ void stats0_kernel(const float* __restrict__ x, float2* __restrict__ st, int rows) {
    int row = blockIdx.x * 8 + (threadIdx.x >> 5);
    int lane = threadIdx.x & 31;
    if (row >= rows) return;
    const float2* p = (const float2*)(x + (size_t)row * DD);
    float s = 0.f, s2 = 0.f;
#pragma unroll
    for (int i = 0; i < 6; i++) {
        float2 v = p[lane + 32 * i];
        s += v.x + v.y;
        s2 += v.x * v.x + v.y * v.y;
    }
#pragma unroll
    for (int o = 16; o; o >>= 1) {
        s += __shfl_xor_sync(0xffffffffu, s, o);
        s2 += __shfl_xor_sync(0xffffffffu, s2, o);
    }
    if (lane == 0) st[row] = make_float2(s, s2);
    else if (lane < 6) st[(size_t)lane * SROWS + row] = make_float2(0.f, 0.f);
}
// layernorm bf16 in -> e4m3 out (x SC_LN), 1 warp per row (k side-stream only)
__global__ void ln_bf_f8(const __nv_bfloat16* __restrict__ in, uint8_t* __restrict__ out,
                         const float* __restrict__ w, const float* __restrict__ b, int rows) {
    int row = blockIdx.x * 8 + (threadIdx.x >> 5);
    int lane = threadIdx.x & 31;
    if (row >= rows) return;
    const __nv_bfloat162* p = (const __nv_bfloat162*)(in + (size_t)row * DD);
    float2 v[6];
    float s = 0.f;
#pragma unroll
    for (int i = 0; i < 6; i++) {
        __nv_bfloat162 t = p[lane + 32 * i];
        v[i].x = __bfloat162float(t.x);
        v[i].y = __bfloat162float(t.y);
        s += v[i].x + v[i].y;
    }
#pragma unroll
    for (int o = 16; o; o >>= 1) s += __shfl_xor_sync(0xffffffffu, s, o);
    float mu = s * (1.0f / DD);
    float var = 0.f;
#pragma unroll
    for (int i = 0; i < 6; i++) {
        float dx = v[i].x - mu, dy = v[i].y - mu;
        var += dx * dx + dy * dy;
    }
#pragma unroll
    for (int o = 16; o; o >>= 1) var += __shfl_xor_sync(0xffffffffu, var, o);
    float inv = rsqrtf(var * (1.0f / DD) + 1e-6f);
    uint8_t* q = out + (size_t)row * DD;
    const float2* w2 = (const float2*)w;
    const float2* b2 = (const float2*)b;
#pragma unroll
    for (int i = 0; i < 6; i++) {
        int c = lane + 32 * i;
        float2 ww = w2[c], bb = b2[c];
        float o0 = ((v[i].x - mu) * inv * ww.x + bb.x) * SC_LN;
        float o1 = ((v[i].y - mu) * inv * ww.y + bb.y) * SC_LN;
        *(uint16_t*)(q + 2 * c) = pack_e4m3(o0, o1);
    }
}
// softmax: bf16 in (stride MPAD) -> e4m3 out x SC_ATTN
__global__ void softmax_bf_f8(const __nv_bfloat16* __restrict__ s, uint8_t* __restrict__ out,
                              int rows, int Mk) {
    int row = blockIdx.x * 8 + (threadIdx.x >> 5);
    int lane = threadIdx.x & 31;
    if (row >= rows) return;
    const __nv_bfloat162* p = (const __nv_bfloat162*)(s + (size_t)row * MPAD);
    float2 v[10];
    float mx = -1e30f;
#pragma unroll
    for (int i = 0; i < 10; i++) {
        int j = 2 * (lane + 32 * i);
        __nv_bfloat162 t = p[lane + 32 * i];
        v[i].x = (j < Mk) ? __bfloat162float(t.x) : -1e30f;
        v[i].y = (j + 1 < Mk) ? __bfloat162float(t.y) : -1e30f;
        mx = fmaxf(mx, fmaxf(v[i].x, v[i].y));
    }
#pragma unroll
    for (int o = 16; o; o >>= 1) mx = fmaxf(mx, __shfl_xor_sync(0xffffffffu, mx, o));
    float sum = 0.f;
#pragma unroll
    for (int i = 0; i < 10; i++) {
        v[i].x = __expf(v[i].x - mx);
        v[i].y = __expf(v[i].y - mx);
        sum += v[i].x + v[i].y;
    }
#pragma unroll
    for (int o = 16; o; o >>= 1) sum += __shfl_xor_sync(0xffffffffu, sum, o);
    float r = SC_ATTN / sum;
    uint8_t* q = out + (size_t)row * MPAD;
#pragma unroll
    for (int i = 0; i < 10; i++) {
        int j = 2 * (lane + 32 * i);
        float o0 = (j < Mk) ? v[i].x * r : 0.f;
        float o1 = (j + 1 < Mk) ? v[i].y * r : 0.f;
        *(uint16_t*)(q + j) = pack_e4m3(o0, o1);
    }
}

// ---------------- host orchestration ----------------
static inline int ceil_div(int a, int b) { return (a + b - 1) / b; }

extern "C" void kernel_launch(void* const* d_in, const int* in_sizes, int n_in,
                              void* d_out, int out_size) {
    const float* x_in    = (const float*)d_in[0];
    const float* norm1_w = (const float*)d_in[1];
    const float* norm1_b = (const float*)d_in[2];
    const float* qkv_w   = (const float*)d_in[3];
    const float* qkv_b   = (const float*)d_in[4];
    const float* qn_w    = (const float*)d_in[5];
    const float* qn_b    = (const float*)d_in[6];
    const float* kn_w    = (const float*)d_in[7];
    const float* kn_b    = (const float*)d_in[8];
    const float* an_w    = (const float*)d_in[9];
    const float* an_b    = (const float*)d_in[10];
    const float* proj_w  = (const float*)d_in[11];
    const float* proj_b  = (const float*)d_in[12];
    const float* ls1     = (const float*)d_in[13];
    const float* norm2_w = (const float*)d_in[14];
    const float* norm2_b = (const float*)d_in[15];
    const float* fc1_w   = (const float*)d_in[16];
    const float* fc1_b   = (const float*)d_in[17];
    const float* fc2_w   = (const float*)d_in[18];
    const float* fc2_b   = (const float*)d_in[19];
    const float* ls2     = (const float*)d_in[20];
    float* out = (float*)d_out;

    cudaFuncSetAttribute(mma_gemm_nt, cudaFuncAttributeMaxDynamicSharedMemorySize, SMEM_G);
    cudaFuncSetAttribute(gemm_lnA, cudaFuncAttributeMaxDynamicSharedMemorySize, SMEM_LNA);

    static cudaStream_t s1 = 0, s2 = 0;
    static cudaEvent_t e_mem = 0, ek[LL], ev[LL];
    static int init_done = 0;
    if (!init_done) {
        cudaStreamCreateWithFlags(&s1, cudaStreamNonBlocking);
        cudaStreamCreateWithFlags(&s2, cudaStreamNonBlocking);
        cudaEventCreateWithFlags(&e_mem, cudaEventDisableTiming);
        for (int l = 0; l < LL; l++) {
            cudaEventCreateWithFlags(&ek[l], cudaEventDisableTiming);
            cudaEventCreateWithFlags(&ev[l], cudaEventDisableTiming);
        }
        init_done = 1;
    }

    float *px, *phist;
    __nv_bfloat16 *pqbf, *pkbf, *pscbf;
    uint8_t *pmem, *pattn, *ph, *pk8L, *pvTL;
    uint8_t *wqkv, *wproj, *wfc1, *wfc2;
    float2 *pxs1, *pxs2, *pqst, *ppst;
    cudaGetSymbolAddress((void**)&px, g_x);
    cudaGetSymbolAddress((void**)&phist, g_hist);
    cudaGetSymbolAddress((void**)&pqbf, g_qbf);
    cudaGetSymbolAddress((void**)&pkbf, g_kbf);
    cudaGetSymbolAddress((void**)&pscbf, g_scbf);
    cudaGetSymbolAddress((void**)&pmem, g_mem8);
    cudaGetSymbolAddress((void**)&pattn, g_attn8);
    cudaGetSymbolAddress((void**)&ph, g_h8);
    cudaGetSymbolAddress((void**)&pk8L, g_k8L);
    cudaGetSymbolAddress((void**)&pvTL, g_vT8L);
    cudaGetSymbolAddress((void**)&wqkv, g_wqkv8);
    cudaGetSymbolAddress((void**)&wproj, g_wproj8);
    cudaGetSymbolAddress((void**)&wfc1, g_wfc18);
    cudaGetSymbolAddress((void**)&wfc2, g_wfc28);
    cudaGetSymbolAddress((void**)&pxs1, g_xs1);
    cudaGetSymbolAddress((void**)&pxs2, g_xs2);
    cudaGetSymbolAddress((void**)&pqst, g_qst);
    cudaGetSymbolAddress((void**)&ppst, g_pst);

    const float scale = 1.0f / sqrtf((float)DD);
    const int nXND = BB * NN * DD;
    const int rowsX = BB * NN;

    const float aQK   = 1.0f / (SC_LN * SC_W);
    const float aMEMW = 1.0f / (SC_MEM * SC_W);
    const float aSC   = scale / (SC_LN * SC_LN);
    const float aPV   = 1.0f / (SC_ATTN * SC_V);
    const float aFC1  = 1.0f / (SC_LN * SC_W);
    const float aFC2  = 1.0f / (SC_H * SC_W);

    {
        int n1 = LL * 3 * DD * DD / 2;
        cvt_w8_kernel<<<ceil_div(n1, 256), 256>>>(wqkv, qkv_w, n1);
        int n2 = LL * DD * DD / 2;
        cvt_w8_kernel<<<ceil_div(n2, 256), 256>>>(wproj, proj_w, n2);
        int n3 = LL * HH * DD / 2;
        cvt_w8_kernel<<<ceil_div(n3, 256), 256>>>(wfc1, fc1_w, n3);
        cvt_w8_kernel<<<ceil_div(n3, 256), 256>>>(wfc2, fc2_w, n3);
    }

    copy_kernel<<<ceil_div(nXND, 256), 256>>>(px, x_in, nXND);

    for (int r = 0; r < NRPT; r++) {
        int Mk = NN + r;
        int rowsM = BB * Mk;
        int mtX = ceil_div(rowsX, 128);
        int mtM = ceil_div(rowsM, 128);
        int ntMk = ceil_div(Mk, 128);
        long zK8 = (long)BB * MMAX * DD;
        long zVT = (long)BB * DD * MPAD;

        save_cls_kernel<<<ceil_div(BB * DD, 256), 256>>>(px, phist + (size_t)r * BB * DD);
        restore_patches_kernel<<<ceil_div(nXND, 256), 256>>>(px, x_in);
        build_mem8_kernel<<<ceil_div(BB * Mk * DD / 2, 256), 256>>>(pmem, px, phist, Mk);
        stats0_kernel<<<ceil_div(rowsX, 8), 256>>>(px, pxs1, rowsX);
        cudaEventRecord(e_mem, 0);
        cudaStreamWaitEvent(s1, e_mem, 0);
        cudaStreamWaitEvent(s2, e_mem, 0);

        // side streams: all layers' k8 (s1) and vT8 (s2)
        for (int l = 0; l < LL; l++) {
            const uint8_t* Wk = wqkv + (size_t)l * 3 * DD * DD + (size_t)DD * DD;
            const float* bk = qkv_b + (size_t)l * 3 * DD + DD;
            mma_gemm_nt<<<dim3(3, mtM, 1), 256, SMEM_G, s1>>>(
                pmem, Wk, bk, 0, 0, pkbf, 0, 0, rowsM, DD, DD, DD, DD, DD, DD,
                0, 0, 0, aMEMW, 1.f, 4);
            ln_bf_f8<<<ceil_div(rowsM, 8), 256, 0, s1>>>(
                pkbf, pk8L + (size_t)l * zK8, kn_w + l * DD, kn_b + l * DD, rowsM);
            cudaEventRecord(ek[l], s1);
        }
        for (int l = 0; l < LL; l++) {
            const uint8_t* Wv = wqkv + (size_t)l * 3 * DD * DD + (size_t)2 * DD * DD;
            const float* bv = qkv_b + (size_t)l * 3 * DD + 2 * DD;
            mma_gemm_nt<<<dim3(MPAD / 128, 3, BB), 256, SMEM_G, s2>>>(
                Wv, pmem, bv, 0, 0, pvTL + (size_t)l * zVT, 0, 0, DD, Mk, MPAD, DD, DD, DD, MPAD,
                0, (long)Mk * DD, (long)DD * MPAD, aMEMW, SC_V, 3);
            cudaEventRecord(ev[l], s2);
        }

        // main chain
        for (int l = 0; l < LL; l++) {
            const uint8_t* Wq = wqkv + (size_t)l * 3 * DD * DD;
            const float* bq = qkv_b + (size_t)l * 3 * DD;

            // q(bf16) = LN1(x) @ Wq^T + bq ; stats -> qst
            gemm_lnA<<<dim3(3, mtX, 1), 256, SMEM_LNA>>>(
                px, 1, Wq, bq, 0, 0, norm1_w + l * DD, norm1_b + l * DD,
                pxs1, 0, pqst, 0, pqbf, rowsX, DD, DD, DD, DD, DD,
                0, 0, 0, aQK, 1.f, 4);
            // scores(bf16) = scale * LNq(q) @ k8^T
            cudaStreamWaitEvent(0, ek[l], 0);
            gemm_lnA<<<dim3(ntMk, ceil_div(NN, 128), BB), 256, SMEM_LNA>>>(
                pqbf, 0, pk8L + (size_t)l * zK8, 0, 0, 0, qn_w + l * DD, qn_b + l * DD,
                pqst, NN, 0, 0, pscbf, NN, Mk, MPAD, DD, DD, MPAD,
                (long)NN * DD, (long)Mk * DD, (long)NN * MPAD, aSC, 1.f, 4);
            softmax_bf_f8<<<ceil_div(BB * NN, 8), 256>>>(pscbf, pattn, BB * NN, Mk);
            // prod(bf16) = attn8 @ vT8^T ; stats -> pst
            cudaStreamWaitEvent(0, ev[l], 0);
            mma_gemm_nt<<<dim3(3, ceil_div(NN, 128), BB), 256, SMEM_G>>>(
                pattn, pvTL + (size_t)l * zVT, 0, 0, 0, pqbf, ppst, NN,
                NN, DD, DD, MPAD, MPAD, MPAD, DD,
                (long)NN * MPAD, (long)DD * MPAD, (long)NN * DD, aPV, 1.f, 4);
            // x += (LNa(prod) @ Wproj^T + pb)*ls1 ; stats(new x) -> xs2
            gemm_lnA<<<dim3(3, mtX, 1), 256, SMEM_LNA>>>(
                pqbf, 0, wproj + (size_t)l * DD * DD, proj_b + l * DD, ls1 + l * DD, px,
                an_w + l * DD, an_b + l * DD, ppst, 0, pxs2, 0, px,
                rowsX, DD, DD, DD, DD, DD, 0, 0, 0, aQK, 1.f, 2);
            // h8 = gelu(LN2(x) @ Wfc1^T + b1) * SC_H
            gemm_lnA<<<dim3(HH / 128, mtX, 1), 256, SMEM_LNA>>>(
                px, 1, wfc1 + (size_t)l * HH * DD, fc1_b + l * HH, 0, 0,
                norm2_w + l * DD, norm2_b + l * DD, pxs2, 0, 0, 0, ph,
                rowsX, HH, HH, DD, DD, HH, 0, 0, 0, aFC1, SC_H, 1);
            // x += (h8 @ Wfc2^T + b2)*ls2 ; stats(new x) -> xs1
            mma_gemm_nt<<<dim3(3, mtX, 1), 256, SMEM_G>>>(
                ph, wfc2 + (size_t)l * DD * HH, fc2_b + l * DD, ls2 + l * DD, px, px,
                pxs1, 0, rowsX, DD, DD, HH, HH, HH, DD, 0, 0, 0, aFC2, 1.f, 2);
        }
    }

    copy_kernel<<<ceil_div(nXND, 256), 256>>>(out, px, nXND);
}